// round 17
// baseline (speedup 1.0000x reference)
#include <cuda_runtime.h>
#include <cuda_fp16.h>
#include <cstdint>
#include <cstddef>

#define BN_TOT 12800
#define RNN    512
#define EMB    300
#define EMBP   320
#define NGATE  2048
#define TSTEPS 8
#define K1     832     // 320 + 512
#define K2     1024    // 512 + 512
#define NCTA   296     // 2 CTAs/SM x 148 SMs (must stay co-resident)

// ---------------- persistent device scratch ----------------
__device__ __half g_X[(size_t)TSTEPS * BN_TOT * EMBP];   // tanh(emb), fp16, padded
__device__ __half g_H1[2][(size_t)BN_TOT * RNN];
__device__ __half g_H2[2][(size_t)BN_TOT * RNN];
__device__ float  g_c1[(size_t)BN_TOT * RNN];
__device__ float  g_c2[(size_t)BN_TOT * RNN];
__device__ __half g_W1h[(size_t)NGATE * K1];   // row r = 4*n + gate (i,f,g,o), K-major
__device__ __half g_W2h[(size_t)NGATE * K2];
__device__ float  g_b1[NGATE];
__device__ float  g_b2[NGATE];
__device__ int    g_fl1[TSTEPS][100];          // arrivals (16 = row-block ready)
__device__ int    g_fl2[TSTEPS][100];

// ---------------- helpers ----------------
__device__ __forceinline__ uint32_t smem_u32(const void* p) {
    uint32_t a;
    asm("{ .reg .u64 t; cvta.to.shared.u64 t, %1; cvt.u32.u64 %0, t; }" : "=r"(a) : "l"(p));
    return a;
}
__device__ __forceinline__ void cp16(uint32_t dst, const void* src) {
    asm volatile("cp.async.cg.shared.global [%0], [%1], 16;\n" :: "r"(dst), "l"(src));
}
__device__ __forceinline__ void cp_commit() {
    asm volatile("cp.async.commit_group;\n" ::: "memory");
}
__device__ __forceinline__ void ldsm_x4(uint32_t* r, uint32_t addr) {
    asm volatile("ldmatrix.sync.aligned.m8n8.x4.shared.b16 {%0,%1,%2,%3}, [%4];"
                 : "=r"(r[0]), "=r"(r[1]), "=r"(r[2]), "=r"(r[3]) : "r"(addr));
}
__device__ __forceinline__ void mma16816(float* c, const uint32_t* a, uint32_t b0, uint32_t b1) {
    asm volatile(
        "mma.sync.aligned.m16n8k16.row.col.f32.f16.f16.f32 "
        "{%0,%1,%2,%3},{%4,%5,%6,%7},{%8,%9},{%0,%1,%2,%3};"
        : "+f"(c[0]), "+f"(c[1]), "+f"(c[2]), "+f"(c[3])
        : "r"(a[0]), "r"(a[1]), "r"(a[2]), "r"(a[3]), "r"(b0), "r"(b1));
}
__device__ __forceinline__ float tanh_fast(float x) {
    float y;
    asm("tanh.approx.f32 %0, %1;" : "=f"(y) : "f"(x));
    return y;
}
__device__ __forceinline__ float sigm_fast(float x) {
    return fmaf(tanh_fast(0.5f * x), 0.5f, 0.5f);
}
__device__ __forceinline__ void spin16(int* f) {
    int v;
    do { asm volatile("ld.acquire.gpu.u32 %0, [%1];" : "=r"(v) : "l"(f) : "memory"); } while (v < 16);
}

#define STAGE_BYTES 32768
#define SMEM_BYTES  98304

// ---------------- merged prep kernel: pack W1 + pack W2 + embed + zero flags ----------------
#define W1PAIRS (NGATE * (K1 / 2))
#define W2PAIRS (NGATE * (K2 / 2))
#define EPAIRS  (TSTEPS * BN_TOT * (EMBP / 2))
#define PREP_TOT (W1PAIRS + W2PAIRS + EPAIRS)
#define NFLAGS  (2 * TSTEPS * 100)

__global__ void prep_all(const int* __restrict__ sent, const float* __restrict__ w2v,
                         const float* __restrict__ Wih1, const float* __restrict__ Whh1,
                         const float* __restrict__ bih1, const float* __restrict__ bhh1,
                         const float* __restrict__ Wih2, const float* __restrict__ Whh2,
                         const float* __restrict__ bih2, const float* __restrict__ bhh2) {
    int gid = blockIdx.x * blockDim.x + threadIdx.x;
    if (gid < W1PAIRS) {
        int idx = gid;
        int r = idx / (K1 / 2), k = (idx - r * (K1 / 2)) * 2;
        int src = (r & 3) * RNN + (r >> 2);
        float v0 = 0.f, v1 = 0.f;
        if (k < EMB) {
            v0 = Wih1[(size_t)src * EMB + k];
            if (k + 1 < EMB) v1 = Wih1[(size_t)src * EMB + k + 1];
        } else if (k >= EMBP) {
            v0 = Whh1[(size_t)src * RNN + (k - EMBP)];
            v1 = Whh1[(size_t)src * RNN + (k + 1 - EMBP)];
        }
        ((__half2*)g_W1h)[idx] = __floats2half2_rn(v0, v1);
        if (k == 0) g_b1[r] = bih1[src] + bhh1[src];
    } else if (gid < W1PAIRS + W2PAIRS) {
        int idx = gid - W1PAIRS;
        int r = idx / (K2 / 2), k = (idx - r * (K2 / 2)) * 2;
        int src = (r & 3) * RNN + (r >> 2);
        float v0, v1;
        if (k < RNN) { v0 = Wih2[(size_t)src * RNN + k];        v1 = Wih2[(size_t)src * RNN + k + 1]; }
        else         { v0 = Whh2[(size_t)src * RNN + (k - RNN)]; v1 = Whh2[(size_t)src * RNN + (k + 1 - RNN)]; }
        ((__half2*)g_W2h)[idx] = __floats2half2_rn(v0, v1);
        if (k == 0) g_b2[r] = bih2[src] + bhh2[src];
    } else if (gid < PREP_TOT) {
        int idx = gid - W1PAIRS - W2PAIRS;
        int row = idx / (EMBP / 2);
        int e   = (idx - row * (EMBP / 2)) * 2;
        int t = row / BN_TOT, bn = row - t * BN_TOT;
        int id = __ldg(&sent[bn * TSTEPS + t]);
        float v0 = 0.f, v1 = 0.f;
        if (e < EMB) {
            const float* w = &w2v[(size_t)id * EMB + e];
            v0 = tanh_fast(w[0]);
            v1 = tanh_fast(w[1]);
        }
        ((__half2*)g_X)[idx] = __floats2half2_rn(v0, v1);
    } else if (gid < PREP_TOT + NFLAGS) {
        int idx = gid - PREP_TOT;
        if (idx < TSTEPS * 100) ((int*)g_fl1)[idx] = 0;
        else                    ((int*)g_fl2)[idx - TSTEPS * 100] = 0;
    }
}

// ---------------- fused fp16 HMMA GEMM + LSTM cell (device core, R14/R16 mainloop) ----------------
// Block tile 128x128x64. 8 warps 4(M)x2(N). 3-stage cp.async, one block barrier
// per chunk, per-warp rotated ks order. Runtime KT/FIRST/LAST for persistent use.
// c-state uses __ldcg/__stcg (L2 coherence point) — cross-SM reuse within one launch.
template<int SPLIT, int S0, int WLD>
__device__ __forceinline__ void gemm_item(
    const __half* __restrict__ A0, const __half* __restrict__ A1,
    const __half* __restrict__ Wp, const float* __restrict__ bias,
    float* __restrict__ Cst, __half* __restrict__ Hd, float* __restrict__ out,
    int rowBase, int colBase, int KT, bool FIRST, bool LAST, char* smem)
{
    const uint32_t sb = smem_u32(smem);
    const int tid = threadIdx.x, lane = tid & 31, warp = tid >> 5;
    const int wm = warp >> 1, wn = warp & 1;
    const int lrow = lane & 15, lhalf = lane >> 4;

    float acc[2][8][4];
    #pragma unroll
    for (int a = 0; a < 2; a++)
        #pragma unroll
        for (int b = 0; b < 8; b++)
            #pragma unroll
            for (int c = 0; c < 4; c++) acc[a][b][c] = 0.f;

    const int r0 = tid >> 3;
    const int c0 = tid & 7;
    const uint32_t d0 = (uint32_t)((r0 * 8 + (c0 ^ (r0 & 7))) << 4);
    const __half* baseA0 = A0 + (size_t)(rowBase + r0) * S0  + c0 * 8;
    const __half* baseA1 = A1 + (size_t)(rowBase + r0) * RNN + c0 * 8;
    const __half* baseB  = Wp + (size_t)(colBase + r0) * WLD + c0 * 8;

    auto issue = [&](int chunk, int stg) {
        uint32_t base = sb + stg * STAGE_BYTES;
        if (chunk < SPLIT) {
            const __half* s = baseA0 + chunk * 64;
            #pragma unroll
            for (int i = 0; i < 4; i++) cp16(base + d0 + i * 4096, s + (size_t)(32 * i) * S0);
        } else {
            const __half* s = baseA1 + (chunk - SPLIT) * 64;
            #pragma unroll
            for (int i = 0; i < 4; i++) cp16(base + d0 + i * 4096, s + (size_t)(32 * i) * RNN);
        }
        const __half* sB = baseB + chunk * 64;
        #pragma unroll
        for (int i = 0; i < 4; i++) cp16(base + 16384 + d0 + i * 4096, sB + (size_t)(32 * i) * WLD);
        cp_commit();
    };

    uint32_t aoff[2], boff[4];
    #pragma unroll
    for (int mt = 0; mt < 2; mt++) aoff[mt] = (uint32_t)((wm * 32 + mt * 16 + lrow) * 128);
    #pragma unroll
    for (int nb = 0; nb < 4; nb++) boff[nb] = (uint32_t)(16384 + (wn * 64 + nb * 16 + lrow) * 128);
    const uint32_t xlo = (uint32_t)(lrow & 7);

    issue(0, 0);
    issue(1, 1);

    #pragma unroll 1
    for (int k = 0; k < KT; k++) {
        const int s = k % 3;
        if (k + 1 < KT) asm volatile("cp.async.wait_group 1;\n" ::: "memory");
        else            asm volatile("cp.async.wait_group 0;\n" ::: "memory");
        __syncthreads();
        if (k + 2 < KT) issue(k + 2, (k + 2) % 3);

        const uint32_t stBase = sb + s * STAGE_BYTES;
        #pragma unroll
        for (int ksi = 0; ksi < 4; ksi++) {
            const int ks = (ksi + warp) & 3;
            const uint32_t xk = ((((uint32_t)(ks << 1) + lhalf) ^ xlo) << 4);
            uint32_t afr[2][4];
            #pragma unroll
            for (int mt = 0; mt < 2; mt++) ldsm_x4(afr[mt], stBase + aoff[mt] + xk);
            uint32_t bfr[4][4];
            #pragma unroll
            for (int nb = 0; nb < 4; nb++) ldsm_x4(bfr[nb], stBase + boff[nb] + xk);
            #pragma unroll
            for (int mt = 0; mt < 2; mt++)
                #pragma unroll
                for (int nb = 0; nb < 4; nb++) {
                    mma16816(acc[mt][2 * nb],     afr[mt], bfr[nb][0], bfr[nb][2]);
                    mma16816(acc[mt][2 * nb + 1], afr[mt], bfr[nb][1], bfr[nb][3]);
                }
        }
    }
    __syncthreads();

    // ---- epilogue: acc -> fp32 smem gate tile -> LSTM cell ----
    float* sC = (float*)smem;                  // 128 x 132
    #pragma unroll
    for (int mt = 0; mt < 2; mt++)
        #pragma unroll
        for (int nt = 0; nt < 8; nt++) {
            int r = wm * 32 + mt * 16 + (lane >> 2);
            int c = wn * 64 + nt * 8 + ((lane & 3) << 1);
            sC[r * 132 + c]           = acc[mt][nt][0];
            sC[r * 132 + c + 1]       = acc[mt][nt][1];
            sC[(r + 8) * 132 + c]     = acc[mt][nt][2];
            sC[(r + 8) * 132 + c + 1] = acc[mt][nt][3];
        }
    __syncthreads();

    #pragma unroll
    for (int i = 0; i < 4; i++) {
        int p4 = tid + i * 256;
        int ml = p4 >> 3;
        int hg = p4 & 7;
        const float* sp = &sC[ml * 132 + hg * 16];
        int gm = rowBase + ml;
        int gh = (colBase >> 2) + hg * 4;
        size_t cidx = (size_t)gm * RNN + gh;
        float4 cold = make_float4(0.f, 0.f, 0.f, 0.f);
        if (!FIRST) cold = __ldcg((const float4*)&Cst[cidx]);
        float cn[4], hv[4];
        #pragma unroll
        for (int j = 0; j < 4; j++) {
            float4 gq = *(const float4*)&sp[j * 4];
            float4 bq = *(const float4*)&bias[colBase + hg * 16 + j * 4];
            float gi = gq.x + bq.x;
            float gf = gq.y + bq.y;
            float gg = gq.z + bq.z;
            float go = gq.w + bq.w;
            float co = (&cold.x)[j];
            cn[j] = sigm_fast(gf) * co + sigm_fast(gi) * tanh_fast(gg);
            hv[j] = sigm_fast(go) * tanh_fast(cn[j]);
        }
        if (!LAST) __stcg((float4*)&Cst[cidx], make_float4(cn[0], cn[1], cn[2], cn[3]));
        if (Hd) {
            __half hh[4];
            #pragma unroll
            for (int j = 0; j < 4; j++) hh[j] = __float2half_rn(hv[j]);
            __stcg((uint2*)&Hd[(size_t)gm * RNN + gh], *(uint2*)hh);
        }
        if (out) *(float4*)&out[cidx] = make_float4(hv[0], hv[1], hv[2], hv[3]);
    }
}

// ---------------- persistent driver: 25600 items, flag-synced ----------------
// Order: l1(0) [0,1600) ; for t=0..6: l2(t) [1600), l1(t+1) [1600) ; l2(7) [1600).
// Item deps precede it by >=1600 items; CTAs process their lists in order -> no deadlock.
__global__ void __launch_bounds__(256, 2) k_persist(float* __restrict__ out) {
    extern __shared__ char smem[];
    #pragma unroll 1
    for (int w = blockIdx.x; w < 25600; w += NCTA) {
        int kind, st, r;
        if (w < 1600)        { kind = 0; st = 0; r = w; }
        else if (w < 24000)  {
            int b = (w - 1600) / 3200, r2 = (w - 1600) - b * 3200;
            if (r2 < 1600) { kind = 1; st = b;     r = r2; }
            else           { kind = 0; st = b + 1; r = r2 - 1600; }
        } else               { kind = 1; st = 7; r = w - 24000; }
        const int nx = r & 15, my = r >> 4;

        if (threadIdx.x == 0) {
            if (kind == 0) { if (st > 0) spin16(&g_fl1[st - 1][my]); }
            else           { spin16(&g_fl1[st][my]); if (st > 0) spin16(&g_fl2[st - 1][my]); }
        }
        __syncthreads();                       // broadcast acquire + smem reuse guard

        if (kind == 0) {
            gemm_item<5, EMBP, K1>(g_X + (size_t)st * BN_TOT * EMBP, g_H1[st & 1],
                                   g_W1h, g_b1, g_c1, g_H1[(st + 1) & 1], nullptr,
                                   my * 128, nx * 128, st ? 13 : 5, st == 0, false, smem);
        } else {
            const bool last = (st == 7);
            gemm_item<8, RNN, K2>(g_H1[(st + 1) & 1], g_H2[st & 1],
                                  g_W2h, g_b2, g_c2, last ? nullptr : g_H2[(st + 1) & 1],
                                  last ? out : nullptr,
                                  my * 128, nx * 128, st ? 16 : 8, st == 0, last, smem);
        }

        __threadfence();                       // each thread's writes visible gpu-wide
        __syncthreads();
        if (threadIdx.x == 0) {
            int* f = (kind == 0) ? &g_fl1[st][my] : &g_fl2[st][my];
            asm volatile("red.release.gpu.global.add.u32 [%0], %1;" :: "l"(f), "r"(1) : "memory");
        }
    }
}

// ---------------- launch ----------------
extern "C" void kernel_launch(void* const* d_in, const int* in_sizes, int n_in,
                              void* d_out, int out_size) {
    (void)in_sizes; (void)n_in; (void)out_size;
    const int*   sentence = (const int*)d_in[0];
    const float* word2vec = (const float*)d_in[1];
    const float* W_ih1 = (const float*)d_in[2];
    const float* W_hh1 = (const float*)d_in[3];
    const float* b_ih1 = (const float*)d_in[4];
    const float* b_hh1 = (const float*)d_in[5];
    const float* W_ih2 = (const float*)d_in[6];
    const float* W_hh2 = (const float*)d_in[7];
    const float* b_ih2 = (const float*)d_in[8];
    const float* b_hh2 = (const float*)d_in[9];
    float* out = (float*)d_out;

    cudaFuncSetAttribute(k_persist, cudaFuncAttributeMaxDynamicSharedMemorySize, SMEM_BYTES);

    prep_all<<<(PREP_TOT + NFLAGS + 255) / 256, 256>>>(sentence, word2vec,
                                                       W_ih1, W_hh1, b_ih1, b_hh1,
                                                       W_ih2, W_hh2, b_ih2, b_hh2);
    k_persist<<<NCTA, 256, SMEM_BYTES>>>(out);
}